// round 1
// baseline (speedup 1.0000x reference)
#include <cuda_runtime.h>

#define B_ROWS  16384
#define IN_DIM  64
#define OUT_DIM 4096
#define BM 128
#define BN 128
#define SLD 132   // padded k-major row stride (floats); 132*4=528 B, 16B-aligned

__device__ float g_xn[B_ROWS];
__device__ float g_cn[OUT_DIM];
__device__ float g_inv[OUT_DIM];

__device__ __forceinline__ unsigned long long pack2(float a, float b) {
    unsigned long long r;
    asm("mov.b64 %0, {%1, %2};" : "=l"(r) : "f"(a), "f"(b));
    return r;
}
__device__ __forceinline__ void fma2(unsigned long long& acc,
                                     unsigned long long a, unsigned long long b) {
    asm("fma.rn.f32x2 %0, %1, %2, %0;" : "+l"(acc) : "l"(a), "l"(b));
}
__device__ __forceinline__ void unpack2(unsigned long long v, float& lo, float& hi) {
    asm("mov.b64 {%0, %1}, %2;" : "=f"(lo), "=f"(hi) : "l"(v));
}

__global__ void xnorm_kernel(const float* __restrict__ x) {
    int r = blockIdx.x * blockDim.x + threadIdx.x;
    if (r >= B_ROWS) return;
    const float4* p = (const float4*)(x + (size_t)r * IN_DIM);
    float s = 0.f;
#pragma unroll
    for (int i = 0; i < IN_DIM / 4; i++) {
        float4 v = p[i];
        s += v.x * v.x + v.y * v.y + v.z * v.z + v.w * v.w;
    }
    g_xn[r] = s;
}

__global__ void cnorm_kernel(const float* __restrict__ c, const float* __restrict__ ls) {
    int r = blockIdx.x * blockDim.x + threadIdx.x;
    if (r >= OUT_DIM) return;
    const float4* p = (const float4*)(c + (size_t)r * IN_DIM);
    float s = 0.f;
#pragma unroll
    for (int i = 0; i < IN_DIM / 4; i++) {
        float4 v = p[i];
        s += v.x * v.x + v.y * v.y + v.z * v.z + v.w * v.w;
    }
    g_cn[r] = s;
    g_inv[r] = __expf(-2.0f * ls[r]);
}

__global__ void __launch_bounds__(256, 2)
rbf_main(const float* __restrict__ x, const float* __restrict__ c,
         float* __restrict__ out) {
    extern __shared__ float smem[];
    float* Xs = smem;                   // [IN_DIM][SLD], k-major
    float* Cs = smem + IN_DIM * SLD;    // [IN_DIM][SLD], k-major

    const int tid = threadIdx.x;
    const int bm = blockIdx.y * BM;
    const int bn = blockIdx.x * BN;

    // ---- global -> shared (transposed), 8 float4 per thread per tile ----
    {
        const int rowp = tid >> 1;      // 0..127
        const int kp   = tid & 1;       // which half of the 16 float4s per row
#pragma unroll
        for (int i = 0; i < 8; i++) {
            int k4 = kp * 8 + i;        // float4 index along K (0..15)
            float4 v = *(const float4*)(x + (size_t)(bm + rowp) * IN_DIM + k4 * 4);
            Xs[(k4 * 4 + 0) * SLD + rowp] = v.x;
            Xs[(k4 * 4 + 1) * SLD + rowp] = v.y;
            Xs[(k4 * 4 + 2) * SLD + rowp] = v.z;
            Xs[(k4 * 4 + 3) * SLD + rowp] = v.w;
            float4 w = *(const float4*)(c + (size_t)(bn + rowp) * IN_DIM + k4 * 4);
            Cs[(k4 * 4 + 0) * SLD + rowp] = w.x;
            Cs[(k4 * 4 + 1) * SLD + rowp] = w.y;
            Cs[(k4 * 4 + 2) * SLD + rowp] = w.z;
            Cs[(k4 * 4 + 3) * SLD + rowp] = w.w;
        }
    }
    __syncthreads();

    const int tx = tid & 15;            // output-col group (8 cols)
    const int ty = tid >> 4;            // output-row group (8 rows)

    unsigned long long acc[8][4];       // [row][col-pair], f32x2 packed
#pragma unroll
    for (int i = 0; i < 8; i++)
#pragma unroll
        for (int j = 0; j < 4; j++) acc[i][j] = 0ULL;

    const float4* Xs4 = (const float4*)Xs;  // row k at float4-index k*33
    const float4* Cs4 = (const float4*)Cs;

#pragma unroll 4
    for (int k = 0; k < IN_DIM; k++) {
        float4 xa = Xs4[k * 33 + ty * 2];
        float4 xb = Xs4[k * 33 + ty * 2 + 1];
        float4 ca = Cs4[k * 33 + tx * 2];
        float4 cb = Cs4[k * 33 + tx * 2 + 1];

        unsigned long long cp[4];
        cp[0] = pack2(ca.x, ca.y);
        cp[1] = pack2(ca.z, ca.w);
        cp[2] = pack2(cb.x, cb.y);
        cp[3] = pack2(cb.z, cb.w);

        float xv[8] = {xa.x, xa.y, xa.z, xa.w, xb.x, xb.y, xb.z, xb.w};
#pragma unroll
        for (int i = 0; i < 8; i++) {
            unsigned long long xp = pack2(xv[i], xv[i]);
#pragma unroll
            for (int j = 0; j < 4; j++) fma2(acc[i][j], xp, cp[j]);
        }
    }

    // ---- epilogue: sq = xn + cn - 2*dot; out = exp(-sq * inv_sigma2) ----
    float xn[8], cn[8], iv[8];
#pragma unroll
    for (int i = 0; i < 8; i++) xn[i] = g_xn[bm + ty * 8 + i];
#pragma unroll
    for (int j = 0; j < 8; j++) {
        cn[j] = g_cn[bn + tx * 8 + j];
        iv[j] = g_inv[bn + tx * 8 + j];
    }

#pragma unroll
    for (int i = 0; i < 8; i++) {
        float d[8];
#pragma unroll
        for (int j = 0; j < 4; j++) {
            float lo, hi;
            unpack2(acc[i][j], lo, hi);
            d[2 * j] = lo;
            d[2 * j + 1] = hi;
        }
        float r[8];
#pragma unroll
        for (int j = 0; j < 8; j++) {
            float sq = fmaxf(xn[i] + cn[j] - 2.0f * d[j], 0.0f);
            r[j] = __expf(-sq * iv[j]);
        }
        float* o = out + (size_t)(bm + ty * 8 + i) * OUT_DIM + bn + tx * 8;
        *(float4*)(o)     = make_float4(r[0], r[1], r[2], r[3]);
        *(float4*)(o + 4) = make_float4(r[4], r[5], r[6], r[7]);
    }
}

extern "C" void kernel_launch(void* const* d_in, const int* in_sizes, int n_in,
                              void* d_out, int out_size) {
    const float* x  = (const float*)d_in[0];
    const float* c  = (const float*)d_in[1];
    const float* ls = (const float*)d_in[2];
    float* out = (float*)d_out;
    (void)in_sizes; (void)n_in; (void)out_size;

    const int smem_bytes = 2 * IN_DIM * SLD * (int)sizeof(float);
    cudaFuncSetAttribute(rbf_main, cudaFuncAttributeMaxDynamicSharedMemorySize, smem_bytes);

    xnorm_kernel<<<B_ROWS / 256, 256>>>(x);
    cnorm_kernel<<<OUT_DIM / 256, 256>>>(c, ls);

    dim3 grid(OUT_DIM / BN, B_ROWS / BM);
    rbf_main<<<grid, 256, smem_bytes>>>(x, c, out);
}

// round 3
// speedup vs baseline: 1.6925x; 1.6925x over previous
#include <cuda_runtime.h>
#include <cuda_bf16.h>
#include <cstdint>

#define B_ROWS 16384
#define IN_DIM 64
#define OUT_DIM 4096
#define BM 128
#define BN 128

// ---- device-global scratch (alloc-guard-safe) ----
__device__ __nv_bfloat16 g_xhi[B_ROWS * IN_DIM];
__device__ __nv_bfloat16 g_xlo[B_ROWS * IN_DIM];
__device__ __nv_bfloat16 g_chi[OUT_DIM * IN_DIM];
__device__ __nv_bfloat16 g_clo[OUT_DIM * IN_DIM];
__device__ float g_xn[B_ROWS];
__device__ float g_cn[OUT_DIM];
__device__ float g_iv[OUT_DIM];

// ---- smem layout (bytes) ----
#define SA_HI 0
#define SA_LO 16384
#define SB_HI 32768
#define SB_LO 49152
#define S_XN  65536
#define S_CN  66048
#define S_IV  66560
#define SMEM_TOTAL 67072

__device__ __forceinline__ uint32_t s2u(const void* p) {
    uint32_t a;
    asm("{ .reg .u64 t; cvta.to.shared.u64 t, %1; cvt.u32.u64 %0, t; }" : "=r"(a) : "l"(p));
    return a;
}

__device__ __forceinline__ void ldm_x4(uint32_t* r, uint32_t addr) {
    asm volatile("ldmatrix.sync.aligned.m8n8.x4.shared.b16 {%0,%1,%2,%3}, [%4];"
                 : "=r"(r[0]), "=r"(r[1]), "=r"(r[2]), "=r"(r[3]) : "r"(addr));
}

__device__ __forceinline__ void mma16816(float* c, const uint32_t* a,
                                         uint32_t b0, uint32_t b1) {
    asm volatile(
        "mma.sync.aligned.m16n8k16.row.col.f32.bf16.bf16.f32 "
        "{%0,%1,%2,%3}, {%4,%5,%6,%7}, {%8,%9}, {%0,%1,%2,%3};"
        : "+f"(c[0]), "+f"(c[1]), "+f"(c[2]), "+f"(c[3])
        : "r"(a[0]), "r"(a[1]), "r"(a[2]), "r"(a[3]), "r"(b0), "r"(b1));
}

// ---- prep: split f32 -> bf16 hi/lo, row norms, inv_sigma2 ----
__global__ void prep_x(const float* __restrict__ x) {
    int gw = (blockIdx.x * blockDim.x + threadIdx.x) >> 5;
    int lane = threadIdx.x & 31;
    if (gw >= B_ROWS) return;
    float2 v = ((const float2*)x)[gw * 32 + lane];
    __nv_bfloat16 h0 = __float2bfloat16_rn(v.x);
    __nv_bfloat16 h1 = __float2bfloat16_rn(v.y);
    __nv_bfloat16 l0 = __float2bfloat16_rn(v.x - __bfloat162float(h0));
    __nv_bfloat16 l1 = __float2bfloat16_rn(v.y - __bfloat162float(h1));
    __nv_bfloat162 hp; hp.x = h0; hp.y = h1;
    __nv_bfloat162 lp; lp.x = l0; lp.y = l1;
    ((__nv_bfloat162*)g_xhi)[gw * 32 + lane] = hp;
    ((__nv_bfloat162*)g_xlo)[gw * 32 + lane] = lp;
    float s = v.x * v.x + v.y * v.y;
#pragma unroll
    for (int o = 16; o; o >>= 1) s += __shfl_xor_sync(0xffffffffu, s, o);
    if (lane == 0) g_xn[gw] = s;
}

__global__ void prep_c(const float* __restrict__ c, const float* __restrict__ ls) {
    int gw = (blockIdx.x * blockDim.x + threadIdx.x) >> 5;
    int lane = threadIdx.x & 31;
    if (gw >= OUT_DIM) return;
    float2 v = ((const float2*)c)[gw * 32 + lane];
    __nv_bfloat16 h0 = __float2bfloat16_rn(v.x);
    __nv_bfloat16 h1 = __float2bfloat16_rn(v.y);
    __nv_bfloat16 l0 = __float2bfloat16_rn(v.x - __bfloat162float(h0));
    __nv_bfloat16 l1 = __float2bfloat16_rn(v.y - __bfloat162float(h1));
    __nv_bfloat162 hp; hp.x = h0; hp.y = h1;
    __nv_bfloat162 lp; lp.x = l0; lp.y = l1;
    ((__nv_bfloat162*)g_chi)[gw * 32 + lane] = hp;
    ((__nv_bfloat162*)g_clo)[gw * 32 + lane] = lp;
    float s = v.x * v.x + v.y * v.y;
#pragma unroll
    for (int o = 16; o; o >>= 1) s += __shfl_xor_sync(0xffffffffu, s, o);
    if (lane == 0) {
        g_cn[gw] = s;
        g_iv[gw] = __expf(-2.0f * ls[gw]);
    }
}

// ---- main: 128x128 tile, split-bf16 mma.sync, fused exp epilogue ----
__global__ void __launch_bounds__(512, 1)
rbf_mma(float* __restrict__ out) {
    extern __shared__ char smem[];
    const uint32_t sb = s2u(smem);
    const int tid = threadIdx.x;
    const int bn = blockIdx.x * BN;
    const int bm = blockIdx.y * BM;

    // ---- global -> smem, XOR-swizzled (16B chunk q -> q ^ (row&7)) ----
    {
        const uint4* axh = (const uint4*)(g_xhi + (size_t)bm * IN_DIM);
        const uint4* axl = (const uint4*)(g_xlo + (size_t)bm * IN_DIM);
        const uint4* bch = (const uint4*)(g_chi + (size_t)bn * IN_DIM);
        const uint4* bcl = (const uint4*)(g_clo + (size_t)bn * IN_DIM);
#pragma unroll
        for (int l = tid; l < 1024; l += 512) {
            int row = l >> 3, q = l & 7;
            int off = row * 128 + ((q ^ (row & 7)) << 4);
            *(uint4*)(smem + SA_HI + off) = axh[l];
            *(uint4*)(smem + SA_LO + off) = axl[l];
            *(uint4*)(smem + SB_HI + off) = bch[l];
            *(uint4*)(smem + SB_LO + off) = bcl[l];
        }
        if (tid < 128) {
            ((float*)(smem + S_XN))[tid] = g_xn[bm + tid];
            ((float*)(smem + S_CN))[tid] = g_cn[bn + tid];
            ((float*)(smem + S_IV))[tid] = g_iv[bn + tid];
        }
    }
    __syncthreads();

    const int wid = tid >> 5, lane = tid & 31;
    const int wm = wid >> 2, wn = wid & 3;   // 4x4 warp grid, 32x32 warp tiles

    // ldmatrix source rows: lanes 0-15 -> rows +0..15 (k lo-chunk),
    // lanes 16-31 -> rows +0..15 (k hi-chunk)
    const int lrow = lane & 15;
    const int ksel = lane >> 4;

    uint32_t aBase[2], bBase[2];
    int aSz[2], bSz[2];
#pragma unroll
    for (int t = 0; t < 2; t++) {
        int ra = wm * 32 + t * 16 + lrow;       // A rows for mt=t
        aBase[t] = sb + SA_HI + ra * 128;       // (hi; +16384 for lo)
        aSz[t] = ra & 7;
        int rb = wn * 32 + t * 16 + lrow;       // B rows for nt-pair t
        bBase[t] = sb + SB_HI + rb * 128;
        bSz[t] = rb & 7;
    }

    float acc[2][4][4];
#pragma unroll
    for (int i = 0; i < 2; i++)
#pragma unroll
        for (int j = 0; j < 4; j++)
#pragma unroll
            for (int k = 0; k < 4; k++) acc[i][j][k] = 0.f;

#pragma unroll
    for (int ks = 0; ks < 4; ks++) {
        const int kc = ks * 2 + ksel;           // 16B-chunk index along K
        uint32_t Ah[2][4], Al[2][4], Bh[2][4], Bl[2][4];
#pragma unroll
        for (int t = 0; t < 2; t++) {
            uint32_t ao = (uint32_t)((kc ^ aSz[t]) << 4);
            ldm_x4(Ah[t], aBase[t] + ao);
            ldm_x4(Al[t], aBase[t] + 16384 + ao);
            uint32_t bo = (uint32_t)((kc ^ bSz[t]) << 4);
            ldm_x4(Bh[t], bBase[t] + bo);
            ldm_x4(Bl[t], bBase[t] + 16384 + bo);
        }
        // x4 on B covers two n-tiles: regs {0,2} -> nt even, {1,3} -> nt odd
#pragma unroll
        for (int mt = 0; mt < 2; mt++)
#pragma unroll
            for (int p = 0; p < 2; p++) {
                mma16816(acc[mt][p * 2 + 0], Ah[mt], Bh[p][0], Bh[p][2]);
                mma16816(acc[mt][p * 2 + 1], Ah[mt], Bh[p][1], Bh[p][3]);
                mma16816(acc[mt][p * 2 + 0], Ah[mt], Bl[p][0], Bl[p][2]);
                mma16816(acc[mt][p * 2 + 1], Ah[mt], Bl[p][1], Bl[p][3]);
                mma16816(acc[mt][p * 2 + 0], Al[mt], Bh[p][0], Bh[p][2]);
                mma16816(acc[mt][p * 2 + 1], Al[mt], Bh[p][1], Bh[p][3]);
            }
    }

    // ---- epilogue: sq = xn + cn - 2*dot; out = exp(-sq*iv) ----
    const float* xn_s = (const float*)(smem + S_XN);
    const float* cn_s = (const float*)(smem + S_CN);
    const float* iv_s = (const float*)(smem + S_IV);
    const int qr = lane >> 2;          // 0..7
    const int qc = (lane & 3) * 2;     // 0,2,4,6

#pragma unroll
    for (int mt = 0; mt < 2; mt++) {
        int r0 = wm * 32 + mt * 16 + qr;       // local rows r0, r0+8
        float xn0 = xn_s[r0], xn1 = xn_s[r0 + 8];
#pragma unroll
        for (int nt = 0; nt < 4; nt++) {
            int col = wn * 32 + nt * 8 + qc;   // local cols col, col+1
            float cn0 = cn_s[col], cn1 = cn_s[col + 1];
            float iv0 = iv_s[col], iv1 = iv_s[col + 1];
            const float* a = acc[mt][nt];
            float2 v0, v1;
            v0.x = __expf(-fmaxf(fmaf(-2.f, a[0], xn0 + cn0), 0.f) * iv0);
            v0.y = __expf(-fmaxf(fmaf(-2.f, a[1], xn0 + cn1), 0.f) * iv1);
            v1.x = __expf(-fmaxf(fmaf(-2.f, a[2], xn1 + cn0), 0.f) * iv0);
            v1.y = __expf(-fmaxf(fmaf(-2.f, a[3], xn1 + cn1), 0.f) * iv1);
            *(float2*)(out + (size_t)(bm + r0) * OUT_DIM + bn + col) = v0;
            *(float2*)(out + (size_t)(bm + r0 + 8) * OUT_DIM + bn + col) = v1;
        }
    }
}

extern "C" void kernel_launch(void* const* d_in, const int* in_sizes, int n_in,
                              void* d_out, int out_size) {
    const float* x  = (const float*)d_in[0];
    const float* c  = (const float*)d_in[1];
    const float* ls = (const float*)d_in[2];
    float* out = (float*)d_out;
    (void)in_sizes; (void)n_in; (void)out_size;

    cudaFuncSetAttribute(rbf_mma, cudaFuncAttributeMaxDynamicSharedMemorySize, SMEM_TOTAL);

    prep_x<<<B_ROWS / 8, 256>>>(x);
    prep_c<<<OUT_DIM / 8, 256>>>(c, ls);

    dim3 grid(OUT_DIM / BN, B_ROWS / BM);
    rbf_mma<<<grid, 512, SMEM_TOTAL>>>(out);
}

// round 5
// speedup vs baseline: 2.5541x; 1.5091x over previous
#include <cuda_runtime.h>
#include <cuda_bf16.h>
#include <cstdint>

#define B_ROWS 16384
#define IN_DIM 64
#define OUT_DIM 4096
#define BM 128
#define BN 128

// ---- device-global scratch (alloc-guard-safe) ----
__device__ __nv_bfloat16 g_xhi[B_ROWS * IN_DIM];
__device__ __nv_bfloat16 g_xlo[B_ROWS * IN_DIM];
__device__ __nv_bfloat16 g_chi[OUT_DIM * IN_DIM];
__device__ __nv_bfloat16 g_clo[OUT_DIM * IN_DIM];
__device__ float g_xn[B_ROWS];
__device__ float g_cn[OUT_DIM];
__device__ float g_iv[OUT_DIM];

// ---- smem layout (bytes) ----
#define SA_HI 0
#define SA_LO 16384
#define SB_HI 32768
#define SB_LO 49152
#define S_XN  65536
#define S_CN  66048
#define S_IV  66560
#define SMEM_TOTAL 67072

__device__ __forceinline__ uint32_t s2u(const void* p) {
    uint32_t a;
    asm("{ .reg .u64 t; cvta.to.shared.u64 t, %1; cvt.u32.u64 %0, t; }" : "=r"(a) : "l"(p));
    return a;
}

__device__ __forceinline__ void ldm_x4(uint32_t* r, uint32_t addr) {
    asm volatile("ldmatrix.sync.aligned.m8n8.x4.shared.b16 {%0,%1,%2,%3}, [%4];"
                 : "=r"(r[0]), "=r"(r[1]), "=r"(r[2]), "=r"(r[3]) : "r"(addr));
}

__device__ __forceinline__ void mma16816(float* c, const uint32_t* a,
                                         uint32_t b0, uint32_t b1) {
    asm volatile(
        "mma.sync.aligned.m16n8k16.row.col.f32.bf16.bf16.f32 "
        "{%0,%1,%2,%3}, {%4,%5,%6,%7}, {%8,%9}, {%0,%1,%2,%3};"
        : "+f"(c[0]), "+f"(c[1]), "+f"(c[2]), "+f"(c[3])
        : "r"(a[0]), "r"(a[1]), "r"(a[2]), "r"(a[3]), "r"(b0), "r"(b1));
}

// ---- prep (fused): split f32 -> bf16 hi/lo, row norms, inv_sigma2 ----
__global__ void prep_all(const float* __restrict__ x, const float* __restrict__ c,
                         const float* __restrict__ ls) {
    int gw = (blockIdx.x * blockDim.x + threadIdx.x) >> 5;
    int lane = threadIdx.x & 31;
    const float* src;
    __nv_bfloat162 *dhi, *dlo;
    int row;
    if (gw < B_ROWS) {
        row = gw; src = x;
        dhi = (__nv_bfloat162*)g_xhi; dlo = (__nv_bfloat162*)g_xlo;
    } else {
        row = gw - B_ROWS;
        if (row >= OUT_DIM) return;
        src = c;
        dhi = (__nv_bfloat162*)g_chi; dlo = (__nv_bfloat162*)g_clo;
    }
    float2 v = ((const float2*)src)[row * 32 + lane];
    __nv_bfloat16 h0 = __float2bfloat16_rn(v.x);
    __nv_bfloat16 h1 = __float2bfloat16_rn(v.y);
    __nv_bfloat16 l0 = __float2bfloat16_rn(v.x - __bfloat162float(h0));
    __nv_bfloat16 l1 = __float2bfloat16_rn(v.y - __bfloat162float(h1));
    __nv_bfloat162 hp; hp.x = h0; hp.y = h1;
    __nv_bfloat162 lp; lp.x = l0; lp.y = l1;
    dhi[row * 32 + lane] = hp;
    dlo[row * 32 + lane] = lp;
    float s = v.x * v.x + v.y * v.y;
#pragma unroll
    for (int o = 16; o; o >>= 1) s += __shfl_xor_sync(0xffffffffu, s, o);
    if (lane == 0) {
        if (gw < B_ROWS) g_xn[row] = s;
        else { g_cn[row] = s; g_iv[row] = __expf(-2.0f * ls[row]); }
    }
}

// ---- main: 128x128 tile, 256 thr, 2 CTA/SM, split-bf16 mma.sync ----
__global__ void __launch_bounds__(256, 2)
rbf_mma(float* __restrict__ out) {
    extern __shared__ char smem[];
    const uint32_t sb = s2u(smem);
    const int tid = threadIdx.x;
    const int bn = blockIdx.x * BN;
    const int bm = blockIdx.y * BM;

    // ---- global -> smem, XOR-swizzled (16B chunk q -> q ^ (row&7)) ----
    {
        const uint4* axh = (const uint4*)(g_xhi + (size_t)bm * IN_DIM);
        const uint4* axl = (const uint4*)(g_xlo + (size_t)bm * IN_DIM);
        const uint4* bch = (const uint4*)(g_chi + (size_t)bn * IN_DIM);
        const uint4* bcl = (const uint4*)(g_clo + (size_t)bn * IN_DIM);
#pragma unroll
        for (int l = tid; l < 1024; l += 256) {
            int row = l >> 3, q = l & 7;
            int off = row * 128 + ((q ^ (row & 7)) << 4);
            *(uint4*)(smem + SA_HI + off) = axh[l];
            *(uint4*)(smem + SA_LO + off) = axl[l];
            *(uint4*)(smem + SB_HI + off) = bch[l];
            *(uint4*)(smem + SB_LO + off) = bcl[l];
        }
        if (tid < 128) {
            ((float*)(smem + S_XN))[tid] = g_xn[bm + tid];
            ((float*)(smem + S_CN))[tid] = g_cn[bn + tid];
            ((float*)(smem + S_IV))[tid] = g_iv[bn + tid];
        }
    }
    __syncthreads();

    const int wid = tid >> 5, lane = tid & 31;
    const int wm = wid >> 2, wn = wid & 3;   // 2x4 warp grid, 64x32 warp tiles

    const int lrow = lane & 15;
    const int ksel = lane >> 4;              // lanes 16-31 take the odd 16B chunk

    uint32_t aBase[4], bBase[2];
    int aSz[4], bSz[2];
#pragma unroll
    for (int t = 0; t < 4; t++) {
        int ra = wm * 64 + t * 16 + lrow;
        aBase[t] = sb + SA_HI + ra * 128;
        aSz[t] = ra & 7;
    }
#pragma unroll
    for (int t = 0; t < 2; t++) {
        int rb = wn * 32 + t * 16 + lrow;
        bBase[t] = sb + SB_HI + rb * 128;
        bSz[t] = rb & 7;
    }

    float acc[4][4][4];
#pragma unroll
    for (int i = 0; i < 4; i++)
#pragma unroll
        for (int j = 0; j < 4; j++)
#pragma unroll
            for (int k = 0; k < 4; k++) acc[i][j][k] = 0.f;

#pragma unroll
    for (int ks = 0; ks < 4; ks++) {
        const int kc = ks * 2 + ksel;        // 16B-chunk index along K
        uint32_t Ah[4][4], Bh[2][4];
#pragma unroll
        for (int t = 0; t < 4; t++) ldm_x4(Ah[t], aBase[t] + ((uint32_t)(kc ^ aSz[t]) << 4));
#pragma unroll
        for (int t = 0; t < 2; t++) ldm_x4(Bh[t], bBase[t] + ((uint32_t)(kc ^ bSz[t]) << 4));
        // hi*hi
#pragma unroll
        for (int mt = 0; mt < 4; mt++)
#pragma unroll
            for (int p = 0; p < 2; p++) {
                mma16816(acc[mt][p * 2 + 0], Ah[mt], Bh[p][0], Bh[p][2]);
                mma16816(acc[mt][p * 2 + 1], Ah[mt], Bh[p][1], Bh[p][3]);
            }
        // hi*lo
        {
            uint32_t Bl[2][4];
#pragma unroll
            for (int t = 0; t < 2; t++)
                ldm_x4(Bl[t], bBase[t] + 16384 + ((uint32_t)(kc ^ bSz[t]) << 4));
#pragma unroll
            for (int mt = 0; mt < 4; mt++)
#pragma unroll
                for (int p = 0; p < 2; p++) {
                    mma16816(acc[mt][p * 2 + 0], Ah[mt], Bl[p][0], Bl[p][2]);
                    mma16816(acc[mt][p * 2 + 1], Ah[mt], Bl[p][1], Bl[p][3]);
                }
        }
        // lo*hi
        {
            uint32_t Al[4][4];
#pragma unroll
            for (int t = 0; t < 4; t++)
                ldm_x4(Al[t], aBase[t] + 16384 + ((uint32_t)(kc ^ aSz[t]) << 4));
#pragma unroll
            for (int mt = 0; mt < 4; mt++)
#pragma unroll
                for (int p = 0; p < 2; p++) {
                    mma16816(acc[mt][p * 2 + 0], Al[mt], Bh[p][0], Bh[p][2]);
                    mma16816(acc[mt][p * 2 + 1], Al[mt], Bh[p][1], Bh[p][3]);
                }
        }
    }

    // ---- epilogue: sq = xn + cn - 2*dot; out = exp(-sq*iv) ----
    const float* xn_s = (const float*)(smem + S_XN);
    const float* cn_s = (const float*)(smem + S_CN);
    const float* iv_s = (const float*)(smem + S_IV);
    const int qr = lane >> 2;          // 0..7
    const int qc = (lane & 3) * 2;     // 0,2,4,6

#pragma unroll
    for (int mt = 0; mt < 4; mt++) {
        int r0 = wm * 64 + mt * 16 + qr;
        float xn0 = xn_s[r0], xn1 = xn_s[r0 + 8];
#pragma unroll
        for (int nt = 0; nt < 4; nt++) {
            int col = wn * 32 + nt * 8 + qc;
            float cn0 = cn_s[col], cn1 = cn_s[col + 1];
            float iv0 = iv_s[col], iv1 = iv_s[col + 1];
            const float* a = acc[mt][nt];
            float2 v0, v1;
            v0.x = __expf(-fmaxf(fmaf(-2.f, a[0], xn0 + cn0), 0.f) * iv0);
            v0.y = __expf(-fmaxf(fmaf(-2.f, a[1], xn0 + cn1), 0.f) * iv1);
            v1.x = __expf(-fmaxf(fmaf(-2.f, a[2], xn1 + cn0), 0.f) * iv0);
            v1.y = __expf(-fmaxf(fmaf(-2.f, a[3], xn1 + cn1), 0.f) * iv1);
            *(float2*)(out + (size_t)(bm + r0) * OUT_DIM + bn + col) = v0;
            *(float2*)(out + (size_t)(bm + r0 + 8) * OUT_DIM + bn + col) = v1;
        }
    }
}

extern "C" void kernel_launch(void* const* d_in, const int* in_sizes, int n_in,
                              void* d_out, int out_size) {
    const float* x  = (const float*)d_in[0];
    const float* c  = (const float*)d_in[1];
    const float* ls = (const float*)d_in[2];
    float* out = (float*)d_out;
    (void)in_sizes; (void)n_in; (void)out_size;

    cudaFuncSetAttribute(rbf_mma, cudaFuncAttributeMaxDynamicSharedMemorySize, SMEM_TOTAL);

    prep_all<<<(B_ROWS + OUT_DIM) / 8, 256>>>(x, c, ls);

    dim3 grid(OUT_DIM / BN, B_ROWS / BM);
    rbf_mma<<<grid, 256, SMEM_TOTAL>>>(out);
}